// round 5
// baseline (speedup 1.0000x reference)
#include <cuda_runtime.h>
#include <cuda_bf16.h>
#include <math.h>
#include <stdint.h>

// Inter-layer scratch + sync (allocation-free rule: __device__ globals).
__device__ float g_out0[729];
__device__ float g_out1[27];
__device__ unsigned g_grp[27];   // per-layer1-chain producer counters (27 each)
__device__ unsigned g_ctr1;      // layer1 completion counter

#define PI_HALF 1.57079632679489662f
#define DEPTH 5
#define STAGE_FLOATS 2048
#define STAGE_BYTES 8192
#define SMEM_DYN (DEPTH * STAGE_BYTES)   // 40 KB -> 5 CTAs/SM, all 729 resident
#define NTHR 128

// ---------------- helpers ----------------
__device__ __forceinline__ uint32_t smem_u32(const void* p) {
    return (uint32_t)__cvta_generic_to_shared(p);
}
__device__ __forceinline__ void cpa16(uint32_t d, const float* s) {
    asm volatile("cp.async.cg.shared.global [%0], [%1], 16;" :: "r"(d), "l"(s) : "memory");
}
__device__ __forceinline__ void cp_commit() {
    asm volatile("cp.async.commit_group;" ::: "memory");
}
__device__ __forceinline__ void cp_wait4() {
    asm volatile("cp.async.wait_group 4;" ::: "memory");
}
__device__ __forceinline__ void l2_prefetch_line(const float* p) {
    asm volatile("prefetch.global.L2 [%0];" :: "l"(p));
}
__device__ __forceinline__ float warp_sum(float v) {
#pragma unroll
    for (int o = 16; o > 0; o >>= 1)
        v += __shfl_down_sync(0xffffffffu, v, o);
    return v;
}
__device__ __forceinline__ void spin_until(const unsigned* c, unsigned target) {
    unsigned v;
    do {
        asm volatile("ld.global.acquire.gpu.u32 %0, [%1];"
                     : "=r"(v) : "l"(c) : "memory");
        if (v >= target) return;
        __nanosleep(128);
    } while (true);
}

// 128-thread issue of one 8 KB stage into ring slot (stage % DEPTH).
// Each thread copies 4 x 16 B; each warp's 4 instructions cover 4 x 512 B
// contiguous chunks; each warp commits ITS OWN group (per-warp wait state).
__device__ __forceinline__ void issue_stage(uint32_t sbase, const float* g,
                                            int stage, int t) {
    const int slot = stage % DEPTH;
    const float* src = g + stage * STAGE_FLOATS + t * 4;
    const uint32_t dst = sbase + slot * STAGE_BYTES + t * 16;
#pragma unroll
    for (int i = 0; i < 4; i++)
        cpa16(dst + i * 2048, src + i * 512);
    cp_commit();
}

// Forward scalar MPS chain, 4 warps cooperating (d split 8 per warp).
// Ring prologue (stages 0..DEPTH-1) must already be issued by all warps.
// Each warp commits exactly one group per iteration (real or empty).
__device__ __forceinline__ float chain_fwd(
    const float* __restrict__ gmid, const float* __restrict__ first,
    const float* __restrict__ last, const float* sc, const float* ss,
    float* vbuf, float (*part)[32], const float* stg, uint32_t sbase, int t)
{
    const int w = t >> 5;      // warp id 0..3
    const int l = t & 31;      // lane = output bond index e
    const int d0 = w * 8;      // this warp's d range [d0, d0+8)

    if (t < 32)
        vbuf[t] = fmaf(first[t], sc[0], first[32 + t] * ss[0]);
    // visibility of vbuf: first iteration's __syncthreads below

#pragma unroll 1
    for (int m = 0; m < 25; m++) {
        cp_wait4();                           // my own quarter of stage m arrived
        __syncthreads();                      // => whole stage m + vbuf visible
        const float* __restrict__ A = stg + (m % DEPTH) * STAGE_FLOATS;
        const float c = sc[m + 1], sn = ss[m + 1];
        float acc = 0.0f;
#pragma unroll
        for (int dd = 0; dd < 8; dd++) {
            const int d = d0 + dd;
            acc = fmaf(vbuf[d], fmaf(A[d * 64 + l], c, A[d * 64 + 32 + l] * sn), acc);
        }
        part[w][l] = acc;
        __syncthreads();                      // A reads + part writes done
        if (m + DEPTH < 25) issue_stage(sbase, gmid, m + DEPTH, t);  // reuse slot m%5
        else                cp_commit();      // empty group keeps wait math exact
        if (w == 0)
            vbuf[l] = part[0][l] + part[1][l] + part[2][l] + part[3][l];
        // vbuf ordered by next iteration's __syncthreads
    }
    __syncthreads();
    float r = 0.0f;
    if (t < 32) {
        float pv = vbuf[t] * fmaf(last[2 * t], sc[26], last[2 * t + 1] * ss[26]);
        r = warp_sum(pv);
    }
    return r;
}

__global__ void reset_kernel() {
    if (threadIdx.x < 27) g_grp[threadIdx.x] = 0;
    if (threadIdx.x == 27) g_ctr1 = 0;
}

// Persistent fused kernel: 729 blocks x 128 threads, one wave.
// Blocks 0-26 additionally run layer 1; block 0 additionally runs the final layer.
__global__ void __launch_bounds__(NTHR)
fused_kernel(const float* __restrict__ img,
             const float* __restrict__ l0f, const float* __restrict__ l0m,
             const float* __restrict__ l0l,
             const float* __restrict__ l1f, const float* __restrict__ l1m,
             const float* __restrict__ l1l,
             const float* __restrict__ ff,  const float* __restrict__ fm,
             const float* __restrict__ fl,
             float* __restrict__ out)
{
    extern __shared__ float stg[];                  // DEPTH x 2048 floats
    __shared__ float sc[27], ss[27], vbuf[32];
    __shared__ float part[4][32];

    const int n = blockIdx.x;
    const int t = threadIdx.x;
    const uint32_t sbase = smem_u32(stg);

    // ---------- Layer 0 ----------
    const float* gm0 = l0m + (long)n * (25 * STAGE_FLOATS);
#pragma unroll
    for (int s = 0; s < DEPTH; s++) issue_stage(sbase, gm0, s, t);

    if (t < 27) {
        const int bh = n / 81, bv = (n / 9) % 9, bd = n % 9;
        const int x = t / 9, y = (t / 3) % 3, z = t % 3;
        const float val = img[(3 * bh + x) * 729 + (3 * bv + y) * 27 + (3 * bd + z)];
        float cv, sv;
        sincosf(PI_HALF * val, &sv, &cv);
        sc[t] = cv; ss[t] = sv;
    }
    __syncthreads();

    float r = chain_fwd(gm0, l0f + n * 64, l0l + n * 64, sc, ss,
                        vbuf, part, stg, sbase, t);
    if (t == 0) {
        g_out0[n] = r;
        __threadfence();
        const int X = n / 81, Y = (n / 9) % 9, Z = n % 9;
        atomicAdd(&g_grp[(X / 3) * 9 + (Y / 3) * 3 + (Z / 3)], 1u);
    }
    if (n >= 27) return;

    // ---------- Layer 1 (blocks 0..26) ----------
    const float* gm1 = l1m + n * (25 * STAGE_FLOATS);
    // Prefetch weights BEFORE spinning: ring prologue + L2 warm of the rest.
#pragma unroll
    for (int s = 0; s < DEPTH; s++) issue_stage(sbase, gm1, s, t);
    {
        const float* pf = gm1 + DEPTH * STAGE_FLOATS;     // remaining 20 stages
        for (int i = t; i < 20 * STAGE_FLOATS / 32; i += NTHR)
            l2_prefetch_line(pf + i * 32);
    }
    if (n == 0) {
        for (int i = t; i < 25 * STAGE_FLOATS / 32; i += NTHR)
            l2_prefetch_line(fm + i * 32);
    }
    spin_until(&g_grp[n], 27u);

    __syncthreads();
    if (t < 27) {
        const int bh = n / 9, bv = (n / 3) % 3, bd = n % 3;
        const int x = t / 9, y = (t / 3) % 3, z = t % 3;
        const float val = __ldcg(&g_out0[(3 * bh + x) * 81 + (3 * bv + y) * 9 + (3 * bd + z)]);
        float cv, sv;
        sincosf(PI_HALF * val, &sv, &cv);
        sc[t] = cv; ss[t] = sv;
    }
    __syncthreads();

    r = chain_fwd(gm1, l1f + n * 64, l1l + n * 64, sc, ss,
                  vbuf, part, stg, sbase, t);
    if (t == 0) {
        g_out1[n] = r;
        __threadfence();
        atomicAdd(&g_ctr1, 1u);
    }
    if (n != 0) return;

    // ---------- Final layer (block 0): right-to-left, output leg at the end ----------
#pragma unroll
    for (int j = 0; j < DEPTH; j++) issue_stage(sbase, fm, 24 - j, t);
    spin_until(&g_ctr1, 27u);

    __syncthreads();
    if (t < 27) {
        // (3,3,3) squeeze of g_out1 is the identity permutation
        float cv, sv;
        sincosf(PI_HALF * __ldcg(&g_out1[t]), &sv, &cv);
        sc[t] = cv; ss[t] = sv;
    }
    if (t < 32) {
        // u_25[d] = last[d,0]*c26 + last[d,1]*s26 (needs sc/ss[26]: same warp wrote it)
        __syncwarp();
        vbuf[t] = fmaf(fl[2 * t], sc[26], fl[2 * t + 1] * ss[26]);
    }
    __syncthreads();

#pragma unroll 1
    for (int j = 0; j < 25; j++) {
        const int stage = 24 - j;
        cp_wait4();
        __syncthreads();
        float un = 0.0f;
        if (t < 32) {
            const float* __restrict__ A = stg + (stage % DEPTH) * STAGE_FLOATS;
            const float c = sc[stage + 1], sn = ss[stage + 1];
            float a0 = 0.0f, a1 = 0.0f;
            // u_new[t] = c*(A[t,0,:]·u) + s*(A[t,1,:]·u); rotated e avoids conflicts
#pragma unroll
            for (int k = 0; k < 32; k++) {
                const int e = (k + t) & 31;
                const float ue = vbuf[e];
                a0 = fmaf(A[t * 64 + e], ue, a0);
                a1 = fmaf(A[t * 64 + 32 + e], ue, a1);
            }
            un = fmaf(a0, c, a1 * sn);
        }
        __syncthreads();
        if (t < 32) vbuf[t] = un;
        if (stage - DEPTH >= 0) issue_stage(sbase, fm, stage - DEPTH, t);
        else                    cp_commit();
        __syncthreads();
    }

    if (t < 32) {
        const float ut = vbuf[t];
#pragma unroll
        for (int o = 0; o < 10; o++) {
            float p = fmaf(ff[o * 32 + t], sc[0], ff[320 + o * 32 + t] * ss[0]) * ut;
            p = warp_sum(p);
            if (t == 0) out[o] = p;
        }
    }
}

extern "C" void kernel_launch(void* const* d_in, const int* in_sizes, int n_in,
                              void* d_out, int out_size)
{
    const float* img      = (const float*)d_in[0];
    const float* l0_first = (const float*)d_in[1];
    const float* l0_mid   = (const float*)d_in[2];
    const float* l0_last  = (const float*)d_in[3];
    const float* l1_first = (const float*)d_in[4];
    const float* l1_mid   = (const float*)d_in[5];
    const float* l1_last  = (const float*)d_in[6];
    const float* f_first  = (const float*)d_in[7];
    const float* f_mid    = (const float*)d_in[8];
    const float* f_last   = (const float*)d_in[9];
    float* out = (float*)d_out;

    reset_kernel<<<1, 32>>>();
    fused_kernel<<<729, NTHR, SMEM_DYN>>>(img, l0_first, l0_mid, l0_last,
                                          l1_first, l1_mid, l1_last,
                                          f_first, f_mid, f_last, out);
}

// round 6
// speedup vs baseline: 1.3567x; 1.3567x over previous
#include <cuda_runtime.h>
#include <cuda_bf16.h>
#include <math.h>
#include <stdint.h>

// Inter-layer scratch + sync (allocation-free rule: __device__ globals).
__device__ float g_out0[729];
__device__ float g_out1[27];
__device__ unsigned g_grp[27];   // per-layer1-chain producer counters (27 each)
__device__ unsigned g_ctr1;      // layer1 completion counter

#define PI_HALF 1.57079632679489662f
#define DEPTH 5
#define STAGE_FLOATS 2048
#define STAGE_BYTES 8192
#define SMEM_DYN (DEPTH * STAGE_BYTES)   // 40 KB -> 5 CTAs/SM, all 729 resident
#define NPIN 530                          // blocks whose l0_mid slab is L2-pinned

// ---------------- helpers ----------------
__device__ __forceinline__ uint32_t smem_u32(const void* p) {
    return (uint32_t)__cvta_generic_to_shared(p);
}
__device__ __forceinline__ uint64_t make_policy_evict_last() {
    uint64_t pol;
    asm("createpolicy.fractional.L2::evict_last.b64 %0, 1.0;" : "=l"(pol));
    return pol;
}
__device__ __forceinline__ uint64_t make_policy_evict_first() {
    uint64_t pol;
    asm("createpolicy.fractional.L2::evict_first.b64 %0, 1.0;" : "=l"(pol));
    return pol;
}
__device__ __forceinline__ void cpa16_pol(uint32_t d, const float* s, uint64_t pol) {
    asm volatile("cp.async.cg.shared.global.L2::cache_hint [%0], [%1], 16, %2;"
                 :: "r"(d), "l"(s), "l"(pol) : "memory");
}
__device__ __forceinline__ void cp_commit() {
    asm volatile("cp.async.commit_group;" ::: "memory");
}
__device__ __forceinline__ void cp_wait4() {
    asm volatile("cp.async.wait_group 4;" ::: "memory");
}
__device__ __forceinline__ float warp_sum(float v) {
#pragma unroll
    for (int o = 16; o > 0; o >>= 1)
        v += __shfl_down_sync(0xffffffffu, v, o);
    return v;
}
__device__ __forceinline__ void spin_until(const unsigned* c, unsigned target) {
    unsigned v;
    do {
        asm volatile("ld.global.acquire.gpu.u32 %0, [%1];"
                     : "=r"(v) : "l"(c) : "memory");
        if (v >= target) return;
        __nanosleep(128);
    } while (true);
}

// Warp-wide issue of one 8 KB stage into ring slot (stage % DEPTH).
// Each lane copies 16 chunks of 16 B (512 B per cp.async wavefront).
__device__ __forceinline__ void issue_stage(uint32_t sbase, const float* g,
                                            int stage, int t, uint64_t pol) {
    const int slot = stage % DEPTH;
    const float* src = g + stage * STAGE_FLOATS + t * 4;
    const uint32_t dst = sbase + slot * STAGE_BYTES + t * 16;
#pragma unroll
    for (int i = 0; i < 16; i++)
        cpa16_pol(dst + i * 512, src + i * 128, pol);
    cp_commit();
}

// Forward scalar MPS chain (one warp). Ring prologue (stages 0..DEPTH-1)
// must already be issued. Every iteration commits exactly one group
// (real or empty) so wait_group 4 always releases exactly stage m.
__device__ __forceinline__ float chain_fwd(
    const float* __restrict__ gmid, const float* __restrict__ first,
    const float* __restrict__ last, const float* sc, const float* ss,
    float* vbuf, const float* stg, uint32_t sbase, int t, uint64_t pol)
{
    vbuf[t] = fmaf(first[t], sc[0], first[32 + t] * ss[0]);
    __syncwarp();

#pragma unroll 1
    for (int m = 0; m < 25; m++) {
        cp_wait4();
        __syncwarp();                         // cross-lane visibility of stage m
        const float* __restrict__ A = stg + (m % DEPTH) * STAGE_FLOATS;
        const float c = sc[m + 1], sn = ss[m + 1];
        float acc = 0.0f;
#pragma unroll
        for (int d = 0; d < 32; d++)
            acc = fmaf(vbuf[d], fmaf(A[d * 64 + t], c, A[d * 64 + 32 + t] * sn), acc);
        __syncwarp();                         // all lanes done reading slot + vbuf
        vbuf[t] = acc;
        if (m + DEPTH < 25) issue_stage(sbase, gmid, m + DEPTH, t, pol);
        else                cp_commit();      // empty group keeps wait_group math exact
        __syncwarp();
    }
    const float pv = vbuf[t] * fmaf(last[2 * t], sc[26], last[2 * t + 1] * ss[26]);
    return warp_sum(pv);
}

__global__ void reset_kernel() {
    if (threadIdx.x < 27) g_grp[threadIdx.x] = 0;
    if (threadIdx.x == 27) g_ctr1 = 0;
}

// Persistent fused kernel: 729 blocks x 32 threads, one wave.
// Blocks 0-26 additionally run layer 1; block 0 additionally runs the final layer.
__global__ void __launch_bounds__(32)
fused_kernel(const float* __restrict__ img,
             const float* __restrict__ l0f, const float* __restrict__ l0m,
             const float* __restrict__ l0l,
             const float* __restrict__ l1f, const float* __restrict__ l1m,
             const float* __restrict__ l1l,
             const float* __restrict__ ff,  const float* __restrict__ fm,
             const float* __restrict__ fl,
             float* __restrict__ out)
{
    extern __shared__ float stg[];                  // DEPTH x 2048 floats
    __shared__ float sc[27], ss[27], vbuf[32];

    const int n = blockIdx.x;
    const int t = threadIdx.x;
    const uint32_t sbase = smem_u32(stg);

    // L2 policy: first NPIN blocks' weights persist across graph replays;
    // the rest stream with evict_first so they never displace the pinned set.
    const uint64_t pol0 = (n < NPIN) ? make_policy_evict_last()
                                     : make_policy_evict_first();
    // ---------- Layer 0 ----------
    const float* gm0 = l0m + (long)n * (25 * STAGE_FLOATS);
#pragma unroll
    for (int s = 0; s < DEPTH; s++) issue_stage(sbase, gm0, s, t, pol0);

    if (t < 27) {
        const int bh = n / 81, bv = (n / 9) % 9, bd = n % 9;
        const int x = t / 9, y = (t / 3) % 3, z = t % 3;
        const float val = img[(3 * bh + x) * 729 + (3 * bv + y) * 27 + (3 * bd + z)];
        float cv, sv;
        sincosf(PI_HALF * val, &sv, &cv);
        sc[t] = cv; ss[t] = sv;
    }
    __syncwarp();

    float r = chain_fwd(gm0, l0f + n * 64, l0l + n * 64, sc, ss,
                        vbuf, stg, sbase, t, pol0);
    if (t == 0) {
        g_out0[n] = r;
        __threadfence();
        const int X = n / 81, Y = (n / 9) % 9, Z = n % 9;
        atomicAdd(&g_grp[(X / 3) * 9 + (Y / 3) * 3 + (Z / 3)], 1u);
    }
    if (n >= 27) return;

    // ---------- Layer 1 (blocks 0..26) ----------
    const uint64_t polw = make_policy_evict_last();   // small sets: keep resident
    const float* gm1 = l1m + n * (25 * STAGE_FLOATS);
    // Prefetch ring prologue BEFORE spinning.
#pragma unroll
    for (int s = 0; s < DEPTH; s++) issue_stage(sbase, gm1, s, t, polw);
    spin_until(&g_grp[n], 27u);

    if (t < 27) {
        const int bh = n / 9, bv = (n / 3) % 3, bd = n % 3;
        const int x = t / 9, y = (t / 3) % 3, z = t % 3;
        const float val = __ldcg(&g_out0[(3 * bh + x) * 81 + (3 * bv + y) * 9 + (3 * bd + z)]);
        float cv, sv;
        sincosf(PI_HALF * val, &sv, &cv);
        sc[t] = cv; ss[t] = sv;
    }
    __syncwarp();

    r = chain_fwd(gm1, l1f + n * 64, l1l + n * 64, sc, ss,
                  vbuf, stg, sbase, t, polw);
    if (t == 0) {
        g_out1[n] = r;
        __threadfence();
        atomicAdd(&g_ctr1, 1u);
    }
    if (n != 0) return;

    // ---------- Final layer (block 0): right-to-left, output leg at the end ----------
#pragma unroll
    for (int j = 0; j < DEPTH; j++) issue_stage(sbase, fm, 24 - j, t, polw);
    spin_until(&g_ctr1, 27u);

    if (t < 27) {
        // (3,3,3) squeeze of g_out1 is the identity permutation
        float cv, sv;
        sincosf(PI_HALF * __ldcg(&g_out1[t]), &sv, &cv);
        sc[t] = cv; ss[t] = sv;
    }
    __syncwarp();

    // u_25[d] = last[d,0]*c26 + last[d,1]*s26
    vbuf[t] = fmaf(fl[2 * t], sc[26], fl[2 * t + 1] * ss[26]);
    __syncwarp();

#pragma unroll 1
    for (int j = 0; j < 25; j++) {
        const int stage = 24 - j;
        cp_wait4();
        __syncwarp();
        const float* __restrict__ A = stg + (stage % DEPTH) * STAGE_FLOATS;
        const float c = sc[stage + 1], sn = ss[stage + 1];
        float a0 = 0.0f, a1 = 0.0f;
        // u_new[t] = c*(A[t,0,:]·u) + s*(A[t,1,:]·u); rotated e keeps LDS conflict-free
#pragma unroll
        for (int k = 0; k < 32; k++) {
            const int e = (k + t) & 31;
            const float ue = vbuf[e];
            a0 = fmaf(A[t * 64 + e], ue, a0);
            a1 = fmaf(A[t * 64 + 32 + e], ue, a1);
        }
        const float un = fmaf(a0, c, a1 * sn);
        __syncwarp();
        vbuf[t] = un;
        if (stage - DEPTH >= 0) issue_stage(sbase, fm, stage - DEPTH, t, polw);
        else                    cp_commit();
        __syncwarp();
    }

    const float ut = vbuf[t];
#pragma unroll
    for (int o = 0; o < 10; o++) {
        float p = fmaf(ff[o * 32 + t], sc[0], ff[320 + o * 32 + t] * ss[0]) * ut;
        p = warp_sum(p);
        if (t == 0) out[o] = p;
    }
}

extern "C" void kernel_launch(void* const* d_in, const int* in_sizes, int n_in,
                              void* d_out, int out_size)
{
    const float* img      = (const float*)d_in[0];
    const float* l0_first = (const float*)d_in[1];
    const float* l0_mid   = (const float*)d_in[2];
    const float* l0_last  = (const float*)d_in[3];
    const float* l1_first = (const float*)d_in[4];
    const float* l1_mid   = (const float*)d_in[5];
    const float* l1_last  = (const float*)d_in[6];
    const float* f_first  = (const float*)d_in[7];
    const float* f_mid    = (const float*)d_in[8];
    const float* f_last   = (const float*)d_in[9];
    float* out = (float*)d_out;

    reset_kernel<<<1, 32>>>();
    fused_kernel<<<729, 32, SMEM_DYN>>>(img, l0_first, l0_mid, l0_last,
                                        l1_first, l1_mid, l1_last,
                                        f_first, f_mid, f_last, out);
}